// round 8
// baseline (speedup 1.0000x reference)
#include <cuda_runtime.h>
#include <math.h>

#define NCTA 128
#define NTH  1024
#define Bsz  256
#define Tlen 1024
#define Hdim 256
#define K2n  128   // Hdim/2 k-pairs (f32x2 lanes)

// Persistent state, exchanged through L2 (double-buffered by step parity).
// u64 layout: [k2][b] packs {h[2k2][b], h[2k2+1][b]}.
__device__ unsigned long long g_h0p[2][K2n * Bsz];
__device__ unsigned long long g_h1p[2][K2n * Bsz];
__device__ float g_xT[Tlen * Bsz];   // x transposed: [t][b]
__device__ unsigned g_cntA = 0;      // barrier line A (h0 publishes)
__device__ unsigned g_cntB = 0;      // barrier line B (h1 publishes)
__device__ unsigned g_done = 0;      // end-of-kernel reset rendezvous

union F2U { float2 f; unsigned long long u; };

__device__ __forceinline__ unsigned long long pack2(float a, float b) {
    F2U v; v.f.x = a; v.f.y = b; return v.u;
}
__device__ __forceinline__ float2 unpack2(unsigned long long u) {
    F2U v; v.u = u; return v.f;
}
// Blackwell packed fp32x2 FMA: 2 exact fp32 MACs per instruction.
__device__ __forceinline__ unsigned long long ffma2(unsigned long long a,
                                                    unsigned long long b,
                                                    unsigned long long c) {
    unsigned long long d;
    asm("fma.rn.f32x2 %0, %1, %2, %3;" : "=l"(d) : "l"(a), "l"(b), "l"(c));
    return d;
}
__device__ __forceinline__ float redsum(unsigned long long a) {
    float2 v = unpack2(a); return v.x + v.y;
}
__device__ __forceinline__ float sigf(float x) {
    return __fdividef(1.0f, 1.0f + __expf(-x));
}
__device__ __forceinline__ float tanhf_(float x) {
    return fmaf(2.0f, sigf(2.0f * x), -1.0f);
}

// Split-phase grid barrier (NCTA co-resident CTAs, 1/SM).
__device__ __forceinline__ void bar_arrive(unsigned* c) {
    __syncthreads();                       // CTA's stores done
    if (threadIdx.x == 0) { __threadfence(); atomicAdd(c, 1u); }
}
__device__ __forceinline__ void bar_wait(unsigned* c, unsigned target) {
    if (threadIdx.x == 0) {
        unsigned v;
        do {
            asm volatile("ld.acquire.gpu.u32 %0, [%1];" : "=r"(v) : "l"(c));
        } while (v < target);
    }
    __syncthreads();
}

// ---- layer-0 matvec slice: 32 k2 per group, writes gate partials to sRed ----
__device__ __forceinline__ void mv_l0(const unsigned long long* __restrict__ hp,
                                      const ulonglong2* __restrict__ sW,
                                      float4* __restrict__ sRed,
                                      int b, int ks) {
    unsigned long long acc[4][2];
    #pragma unroll
    for (int q = 0; q < 4; ++q) { acc[q][0] = 0ull; acc[q][1] = 0ull; }
    const int k0 = ks * 32;
    #pragma unroll 4
    for (int i = 0; i < 32; ++i) {
        int k2 = k0 + i;
        unsigned long long h = __ldcg(hp + k2 * Bsz + b);
        #pragma unroll
        for (int q = 0; q < 4; ++q) {
            ulonglong2 w = sW[k2 * 4 + q];           // broadcast LDS.128
            acc[q][0] = ffma2(h, w.x, acc[q][0]);
            acc[q][1] = ffma2(h, w.y, acc[q][1]);
        }
    }
    #pragma unroll
    for (int j = 0; j < 2; ++j)
        sRed[(ks * 2 + j) * Bsz + b] =
            make_float4(redsum(acc[0][j]), redsum(acc[1][j]),
                        redsum(acc[2][j]), redsum(acc[3][j]));
}

// ---- layer-1 matvec slice over concatenated K = [Wih1 | Whh1] (64 k2'/group) ----
__device__ __forceinline__ void mv_l1(const unsigned long long* __restrict__ ha,
                                      const unsigned long long* __restrict__ hb,
                                      const ulonglong2* __restrict__ sW1,
                                      float4* __restrict__ sRed,
                                      int b, int ks) {
    unsigned long long acc[4][2];
    #pragma unroll
    for (int q = 0; q < 4; ++q) { acc[q][0] = 0ull; acc[q][1] = 0ull; }
    // warp-uniform source select: ks 0-1 -> h0_new (Wih1), ks 2-3 -> h1_prev (Whh1)
    const unsigned long long* __restrict__ hs = (ks < 2) ? ha : hb;
    const int kh0 = (ks < 2) ? 64 * ks : 64 * ks - 128;  // h k2 base
    const int kw0 = 64 * ks;                             // concat weight base
    #pragma unroll 4
    for (int i = 0; i < 64; ++i) {
        unsigned long long h = __ldcg(hs + (kh0 + i) * Bsz + b);
        #pragma unroll
        for (int q = 0; q < 4; ++q) {
            ulonglong2 w = sW1[(kw0 + i) * 4 + q];
            acc[q][0] = ffma2(h, w.x, acc[q][0]);
            acc[q][1] = ffma2(h, w.y, acc[q][1]);
        }
    }
    #pragma unroll
    for (int j = 0; j < 2; ++j)
        sRed[(ks * 2 + j) * Bsz + b] =
            make_float4(redsum(acc[0][j]), redsum(acc[1][j]),
                        redsum(acc[2][j]), redsum(acc[3][j]));
}

__global__ void __launch_bounds__(NTH, 1)
lstm_fused(const float* __restrict__ x,
           const float* __restrict__ Wih0, const float* __restrict__ Whh0,
           const float* __restrict__ bih0, const float* __restrict__ bhh0,
           const float* __restrict__ Wih1, const float* __restrict__ Whh1,
           const float* __restrict__ bih1, const float* __restrict__ bhh1,
           const float* __restrict__ Wlin, const float* __restrict__ blin,
           float* __restrict__ out)
{
    __shared__ ulonglong2 sW0[K2n * 4];        // 8 KB  Whh0 slice (pair-packed)
    __shared__ ulonglong2 sW1[2 * K2n * 4];    // 16 KB [Wih1 | Whh1] concat slice
    __shared__ float4 sRed[8 * Bsz];           // 32 KB [ks*2+j][b] gate partials
    __shared__ float sWx[8], sB0[8], sB1[8];   // per-CTA gate consts [q*2+j]
    __shared__ float sWlin[Hdim];
    __shared__ float sOut[8];

    const int tid = threadIdx.x;
    const int b   = tid & 255;             // this thread's batch
    const int ks  = tid >> 8;              // k-group 0..3 (warp-uniform)
    const int cta = blockIdx.x;
    const int u0  = 2 * cta;               // owned unit pair (both layers)

    // activation role (threads 0..511): unit aj, batch abt
    const int aj  = tid >> 8;              // 0..1 valid when tid < 512
    const int abt = tid & 255;

    // ---- one-time staging ----
    for (int i = cta * NTH + tid; i < Bsz * Tlen; i += NCTA * NTH) {
        int bb = i >> 10, t = i & (Tlen - 1);
        g_xT[t * Bsz + bb] = x[i];
    }
    for (int e = tid; e < K2n * 4; e += NTH) {
        int k2 = e >> 2, q = e & 3;
        int base = (q * Hdim + u0) * Hdim + 2 * k2;
        sW0[e] = make_ulonglong2(pack2(Whh0[base],        Whh0[base + 1]),
                                 pack2(Whh0[base + Hdim], Whh0[base + Hdim + 1]));
    }
    for (int e = tid; e < 2 * K2n * 4; e += NTH) {
        int k2p = e >> 2, q = e & 3;
        const float* W = (k2p < K2n) ? Wih1 : Whh1;
        int k2 = (k2p < K2n) ? k2p : k2p - K2n;
        int base = (q * Hdim + u0) * Hdim + 2 * k2;
        sW1[e] = make_ulonglong2(pack2(W[base],        W[base + 1]),
                                 pack2(W[base + Hdim], W[base + Hdim + 1]));
    }
    if (tid < 8) {
        int q = tid >> 1, j = tid & 1;
        int g = q * Hdim + u0 + j;
        sWx[tid] = Wih0[g];                // input dim == 1
        sB0[tid] = bih0[g] + bhh0[g];
        sB1[tid] = bih1[g] + bhh1[g];
    }
    if (tid < Hdim) sWlin[tid] = Wlin[tid];
    const float bl = __ldg(blin);

    if (tid < Bsz) {                       // zero initial state (parity-0)
        g_h0p[0][cta * Bsz + tid] = 0ull;
        g_h1p[0][cta * Bsz + tid] = 0ull;
    }
    float c0 = 0.f, c1 = 0.f;              // cell state (activation threads)

    // init barrier (line A): staging + zeros visible
    bar_arrive(&g_cntA);
    bar_wait(&g_cntA, 1u * NCTA);

    // ---- prologue: L0(0): h0p[0] -> h0p[1] ----
    {
        mv_l0(g_h0p[0], sW0, sRed, b, ks);
        __syncthreads();
        if (tid < 512) {
            float4 s = sRed[(0 * 2 + aj) * Bsz + abt];
            #pragma unroll
            for (int g = 1; g < 4; ++g) {
                float4 v = sRed[(g * 2 + aj) * Bsz + abt];
                s.x += v.x; s.y += v.y; s.z += v.z; s.w += v.w;
            }
            float xv = g_xT[0 * Bsz + abt];
            float gi = s.x + fmaf(sWx[0*2 + aj], xv, sB0[0*2 + aj]);
            float gf = s.y + fmaf(sWx[1*2 + aj], xv, sB0[1*2 + aj]);
            float gg = s.z + fmaf(sWx[2*2 + aj], xv, sB0[2*2 + aj]);
            float go = s.w + fmaf(sWx[3*2 + aj], xv, sB0[3*2 + aj]);
            float cn = sigf(gf) * c0 + sigf(gi) * tanhf_(gg);
            c0 = cn;
            ((float*)g_h0p[1])[(cta * Bsz + abt) * 2 + aj] = sigf(go) * tanhf_(cn);
        }
        bar_arrive(&g_cntA);
        bar_wait(&g_cntA, 2u * NCTA);
    }

    for (int t = 0; t < Tlen; ++t) {
        const int pr = t & 1, nx = pr ^ 1;

        // ---- L1(t): h0p[nx] (new) + h1p[pr] -> h1p[nx] ----
        mv_l1(g_h0p[nx], g_h1p[pr], sW1, sRed, b, ks);
        __syncthreads();
        if (tid < 512) {
            float4 s = sRed[(0 * 2 + aj) * Bsz + abt];
            #pragma unroll
            for (int g = 1; g < 4; ++g) {
                float4 v = sRed[(g * 2 + aj) * Bsz + abt];
                s.x += v.x; s.y += v.y; s.z += v.z; s.w += v.w;
            }
            float gi = s.x + sB1[0*2 + aj];
            float gf = s.y + sB1[1*2 + aj];
            float gg = s.z + sB1[2*2 + aj];
            float go = s.w + sB1[3*2 + aj];
            float cn = sigf(gf) * c1 + sigf(gi) * tanhf_(gg);
            c1 = cn;
            ((float*)g_h1p[nx])[(cta * Bsz + abt) * 2 + aj] = sigf(go) * tanhf_(cn);
        }
        bar_arrive(&g_cntB);                 // idB = t+1

        // ---- L0(t+1): h0p[nx] -> h0p[pr]  (hides B-barrier latency) ----
        if (t < Tlen - 1) {
            mv_l0(g_h0p[nx], sW0, sRed, b, ks);
            __syncthreads();
            if (tid < 512) {
                float4 s = sRed[(0 * 2 + aj) * Bsz + abt];
                #pragma unroll
                for (int g = 1; g < 4; ++g) {
                    float4 v = sRed[(g * 2 + aj) * Bsz + abt];
                    s.x += v.x; s.y += v.y; s.z += v.z; s.w += v.w;
                }
                float xv = g_xT[(t + 1) * Bsz + abt];
                float gi = s.x + fmaf(sWx[0*2 + aj], xv, sB0[0*2 + aj]);
                float gf = s.y + fmaf(sWx[1*2 + aj], xv, sB0[1*2 + aj]);
                float gg = s.z + fmaf(sWx[2*2 + aj], xv, sB0[2*2 + aj]);
                float go = s.w + fmaf(sWx[3*2 + aj], xv, sB0[3*2 + aj]);
                float cn = sigf(gf) * c0 + sigf(gi) * tanhf_(gg);
                c0 = cn;
                ((float*)g_h0p[pr])[(cta * Bsz + abt) * 2 + aj] = sigf(go) * tanhf_(cn);
            }
            bar_arrive(&g_cntA);             // idA = t+3
        }

        // ---- wait for all h1(t), then output dot for batches {u0, u0+1} ----
        bar_wait(&g_cntB, (unsigned)(t + 1) * NCTA);
        {
            if (tid < 256) {
                const unsigned long long* __restrict__ hc = g_h1p[nx];
                int half = tid >> 7;         // 0..127 -> batch u0, 128..255 -> u0+1
                int kk   = tid & 127;
                int bb   = u0 + half;
                float2 hv = unpack2(__ldcg(hc + kk * Bsz + bb));
                float part = hv.x * sWlin[2*kk] + hv.y * sWlin[2*kk + 1];
                #pragma unroll
                for (int off = 16; off > 0; off >>= 1)
                    part += __shfl_down_sync(0xffffffffu, part, off);
                if ((tid & 31) == 0) sOut[tid >> 5] = part;
            }
            __syncthreads();
            if (tid == 0) {
                out[(u0 + 0) * Tlen + t] = sOut[0] + sOut[1] + sOut[2] + sOut[3] + bl;
                out[(u0 + 1) * Tlen + t] = sOut[4] + sOut[5] + sOut[6] + sOut[7] + bl;
            }
        }

        if (t < Tlen - 1)
            bar_wait(&g_cntA, (unsigned)(t + 3) * NCTA);   // h0(t+1) visible
    }

    // reset counters for next launch
    __syncthreads();
    if (tid == 0) {
        __threadfence();
        unsigned old = atomicAdd(&g_done, 1u);
        if (old == NCTA - 1) {
            atomicExch(&g_cntA, 0u);
            atomicExch(&g_cntB, 0u);
            atomicExch(&g_done, 0u);
        }
    }
}

extern "C" void kernel_launch(void* const* d_in, const int* in_sizes, int n_in,
                              void* d_out, int out_size) {
    (void)in_sizes; (void)n_in; (void)out_size;
    lstm_fused<<<NCTA, NTH>>>(
        (const float*)d_in[0],
        (const float*)d_in[1], (const float*)d_in[2],
        (const float*)d_in[3], (const float*)d_in[4],
        (const float*)d_in[5], (const float*)d_in[6],
        (const float*)d_in[7], (const float*)d_in[8],
        (const float*)d_in[9], (const float*)d_in[10],
        (float*)d_out);
}

// round 9
// speedup vs baseline: 1.1776x; 1.1776x over previous
#include <cuda_runtime.h>
#include <math.h>

#define NCTA 128   // 64 unit-quads x 2 batch-halves
#define NTH  512
#define Bsz  256
#define Tlen 1024
#define Hdim 256
#define K2n  128   // Hdim/2 k-pairs (f32x2 lanes)

// Persistent state, exchanged through L2 (double-buffered by step parity).
// u64 layout: [k2][b] packs {h[2k2][b], h[2k2+1][b]}.
__device__ unsigned long long g_h0p[2][K2n * Bsz];
__device__ unsigned long long g_h1p[2][K2n * Bsz];
__device__ float g_xT[Tlen * Bsz];   // x transposed: [t][b]
__device__ unsigned g_cntA = 0;      // barrier line A (h0 publishes)
__device__ unsigned g_cntB = 0;      // barrier line B (h1 publishes)
__device__ unsigned g_done = 0;      // end-of-kernel reset rendezvous

union F2U { float2 f; unsigned long long u; };

__device__ __forceinline__ unsigned long long pack2(float a, float b) {
    F2U v; v.f.x = a; v.f.y = b; return v.u;
}
__device__ __forceinline__ float2 unpack2(unsigned long long u) {
    F2U v; v.u = u; return v.f;
}
// Blackwell packed fp32x2 FMA: 2 exact fp32 MACs per instruction.
__device__ __forceinline__ unsigned long long ffma2(unsigned long long a,
                                                    unsigned long long b,
                                                    unsigned long long c) {
    unsigned long long d;
    asm("fma.rn.f32x2 %0, %1, %2, %3;" : "=l"(d) : "l"(a), "l"(b), "l"(c));
    return d;
}
__device__ __forceinline__ float redsum(unsigned long long a) {
    float2 v = unpack2(a); return v.x + v.y;
}
__device__ __forceinline__ float sigf(float x) {
    return __fdividef(1.0f, 1.0f + __expf(-x));
}
__device__ __forceinline__ float tanhf_(float x) {
    return fmaf(2.0f, sigf(2.0f * x), -1.0f);
}

// Split-phase grid barrier (NCTA co-resident CTAs).
__device__ __forceinline__ void bar_arrive(unsigned* c) {
    __syncthreads();                       // CTA's stores done
    if (threadIdx.x == 0) { __threadfence(); atomicAdd(c, 1u); }
}
__device__ __forceinline__ void bar_wait(unsigned* c, unsigned target) {
    if (threadIdx.x == 0) {
        unsigned v;
        do {
            asm volatile("ld.acquire.gpu.u32 %0, [%1];" : "=r"(v) : "l"(c));
        } while (v < target);
    }
    __syncthreads();
}

// ---- core matvec: N k2-pairs from hp (stride Bsz), 16 gate-rows from w ----
// acc[r], r = q*4 + ju (gate q, unit-in-quad ju).  MLP-4 software pipeline.
template<int N>
__device__ __forceinline__ void mv_acc(const unsigned long long* __restrict__ hp,
                                       const ulonglong2* __restrict__ w,
                                       unsigned long long* acc) {
    unsigned long long ha[4];
    #pragma unroll
    for (int j = 0; j < 4; ++j) ha[j] = __ldcg(hp + j * Bsz);
    #pragma unroll 2
    for (int i = 0; i < N; i += 4) {
        unsigned long long hb[4];
        #pragma unroll
        for (int j = 0; j < 4; ++j)
            hb[j] = (i + 4 + j < N) ? __ldcg(hp + (i + 4 + j) * Bsz) : 0ull;
        #pragma unroll
        for (int j = 0; j < 4; ++j) {
            const ulonglong2* wj = w + (i + j) * 8;
            #pragma unroll
            for (int r2 = 0; r2 < 8; ++r2) {
                ulonglong2 ww = wj[r2];                 // broadcast LDS.128
                acc[2 * r2 + 0] = ffma2(ha[j], ww.x, acc[2 * r2 + 0]);
                acc[2 * r2 + 1] = ffma2(ha[j], ww.y, acc[2 * r2 + 1]);
            }
        }
        #pragma unroll
        for (int j = 0; j < 4; ++j) ha[j] = hb[j];
    }
}

__global__ void __launch_bounds__(NTH, 1)
lstm_fused(const float* __restrict__ x,
           const float* __restrict__ Wih0, const float* __restrict__ Whh0,
           const float* __restrict__ bih0, const float* __restrict__ bhh0,
           const float* __restrict__ Wih1, const float* __restrict__ Whh1,
           const float* __restrict__ bih1, const float* __restrict__ bhh1,
           const float* __restrict__ Wlin, const float* __restrict__ blin,
           float* __restrict__ out)
{
    // sW0[k2*8 + r2]: .x = rows 2r2 (q=r0>>2, ju=r0&3) k-pair, .y = row 2r2+1
    __shared__ ulonglong2 sW0[K2n * 8];        // 16 KB  Whh0 (16 rows)
    __shared__ ulonglong2 sW1[2 * K2n * 8];    // 32 KB  [Wih1 | Whh1] concat
    __shared__ float4 sRed[16 * 128];          // 32 KB  [ks*4+ju][bloc] gate partials
    __shared__ float sWx[16], sB0[16], sB1[16];// per-CTA gate consts [q*4+ju]
    __shared__ float sWlin[Hdim];
    __shared__ float sOut[8];

    const int tid  = threadIdx.x;
    const int bloc = tid & 127;            // batch within this CTA's half
    const int ks   = tid >> 7;             // k-split group 0..3 (warp-uniform)
    const int cta  = blockIdx.x;
    const int quad = cta >> 1;             // owned unit-quad (both layers)
    const int bh   = cta & 1;              // batch half
    const int u0   = 4 * quad;
    const int bg   = bh * 128 + bloc;      // global batch this thread loads

    // activation role: unit ju = ks, batch ab (all 512 threads active)
    const int aju = ks;                    // unit-in-quad this thread activates
    const int ab  = bloc;
    const int bga = bh * 128 + ab;         // global batch activated
    const int k2h = 2 * quad + (aju >> 1); // h u64 row for owned unit
    const int hpar = aju & 1;              // float slot within u64

    // ---- one-time staging ----
    for (int i = cta * NTH + tid; i < Bsz * Tlen; i += NCTA * NTH) {
        int bb = i >> 10, t = i & (Tlen - 1);
        g_xT[t * Bsz + bb] = x[i];
    }
    for (int e = tid; e < K2n * 8; e += NTH) {
        int k2 = e >> 3, r2 = e & 7;
        int r0 = 2 * r2, r1 = 2 * r2 + 1;
        int g0 = ((r0 >> 2) * Hdim + u0 + (r0 & 3)) * Hdim + 2 * k2;
        int g1 = ((r1 >> 2) * Hdim + u0 + (r1 & 3)) * Hdim + 2 * k2;
        sW0[e] = make_ulonglong2(pack2(Whh0[g0], Whh0[g0 + 1]),
                                 pack2(Whh0[g1], Whh0[g1 + 1]));
    }
    for (int e = tid; e < 2 * K2n * 8; e += NTH) {
        int k2p = e >> 3, r2 = e & 7;
        const float* W = (k2p < K2n) ? Wih1 : Whh1;
        int k2 = k2p & (K2n - 1);
        int r0 = 2 * r2, r1 = 2 * r2 + 1;
        int g0 = ((r0 >> 2) * Hdim + u0 + (r0 & 3)) * Hdim + 2 * k2;
        int g1 = ((r1 >> 2) * Hdim + u0 + (r1 & 3)) * Hdim + 2 * k2;
        sW1[e] = make_ulonglong2(pack2(W[g0], W[g0 + 1]),
                                 pack2(W[g1], W[g1 + 1]));
    }
    if (tid < 16) {                        // [q*4 + ju] = tid
        int q = tid >> 2, ju = tid & 3;
        int g = q * Hdim + u0 + ju;
        sWx[tid] = Wih0[g];                // input dim == 1
        sB0[tid] = bih0[g] + bhh0[g];
        sB1[tid] = bih1[g] + bhh1[g];
    }
    if (tid < Hdim) sWlin[tid] = Wlin[tid];
    const float bl = __ldg(blin);

    if (tid < Bsz) {                       // zero initial state (parity-0)
        g_h0p[0][cta * Bsz + tid] = 0ull;
        g_h1p[0][cta * Bsz + tid] = 0ull;
    }
    float c0 = 0.f, c1 = 0.f;              // cell state for (aju, bga)

    // init barrier (line A): staging + zeros visible
    bar_arrive(&g_cntA);
    bar_wait(&g_cntA, 1u * NCTA);

    unsigned long long acc[16];
    float4 sv;

    // ---- prologue: L0(0): h0p[0] -> h0p[1] ----
    {
        #pragma unroll
        for (int r = 0; r < 16; ++r) acc[r] = 0ull;
        mv_acc<32>(g_h0p[0] + (ks * 32) * Bsz + bg, sW0 + (ks * 32) * 8, acc);
        #pragma unroll
        for (int ju = 0; ju < 4; ++ju)
            sRed[(ks * 4 + ju) * 128 + bloc] =
                make_float4(redsum(acc[0 + ju]), redsum(acc[4 + ju]),
                            redsum(acc[8 + ju]), redsum(acc[12 + ju]));
        __syncthreads();
        sv = sRed[(0 * 4 + aju) * 128 + ab];
        #pragma unroll
        for (int g = 1; g < 4; ++g) {
            float4 v = sRed[(g * 4 + aju) * 128 + ab];
            sv.x += v.x; sv.y += v.y; sv.z += v.z; sv.w += v.w;
        }
        float xv = g_xT[0 * Bsz + bga];
        float gi = sv.x + fmaf(sWx[0 * 4 + aju], xv, sB0[0 * 4 + aju]);
        float gf = sv.y + fmaf(sWx[1 * 4 + aju], xv, sB0[1 * 4 + aju]);
        float gg = sv.z + fmaf(sWx[2 * 4 + aju], xv, sB0[2 * 4 + aju]);
        float go = sv.w + fmaf(sWx[3 * 4 + aju], xv, sB0[3 * 4 + aju]);
        float cn = sigf(gf) * c0 + sigf(gi) * tanhf_(gg);
        c0 = cn;
        ((float*)g_h0p[1])[(k2h * Bsz + bga) * 2 + hpar] = sigf(go) * tanhf_(cn);
        bar_arrive(&g_cntA);
        bar_wait(&g_cntA, 2u * NCTA);
    }

    for (int t = 0; t < Tlen; ++t) {
        const int pr = t & 1, nx = pr ^ 1;

        // ---- L1(t): h0p[nx] (new) + h1p[pr] -> h1p[nx] ----
        {
            #pragma unroll
            for (int r = 0; r < 16; ++r) acc[r] = 0ull;
            // warp-uniform src: ks 0-1 -> h0_new, ks 2-3 -> h1_prev
            const unsigned long long* hs = (ks < 2) ? g_h0p[nx] : g_h1p[pr];
            mv_acc<64>(hs + ((ks & 1) * 64) * Bsz + bg, sW1 + (ks * 64) * 8, acc);
            #pragma unroll
            for (int ju = 0; ju < 4; ++ju)
                sRed[(ks * 4 + ju) * 128 + bloc] =
                    make_float4(redsum(acc[0 + ju]), redsum(acc[4 + ju]),
                                redsum(acc[8 + ju]), redsum(acc[12 + ju]));
            __syncthreads();
            sv = sRed[(0 * 4 + aju) * 128 + ab];
            #pragma unroll
            for (int g = 1; g < 4; ++g) {
                float4 v = sRed[(g * 4 + aju) * 128 + ab];
                sv.x += v.x; sv.y += v.y; sv.z += v.z; sv.w += v.w;
            }
            float gi = sv.x + sB1[0 * 4 + aju];
            float gf = sv.y + sB1[1 * 4 + aju];
            float gg = sv.z + sB1[2 * 4 + aju];
            float go = sv.w + sB1[3 * 4 + aju];
            float cn = sigf(gf) * c1 + sigf(gi) * tanhf_(gg);
            c1 = cn;
            ((float*)g_h1p[nx])[(k2h * Bsz + bga) * 2 + hpar] = sigf(go) * tanhf_(cn);
        }
        bar_arrive(&g_cntB);                 // idB = t+1

        // ---- L0(t+1): h0p[nx] -> h0p[pr]  (hides B-barrier latency) ----
        if (t < Tlen - 1) {
            #pragma unroll
            for (int r = 0; r < 16; ++r) acc[r] = 0ull;
            mv_acc<32>(g_h0p[nx] + (ks * 32) * Bsz + bg, sW0 + (ks * 32) * 8, acc);
            #pragma unroll
            for (int ju = 0; ju < 4; ++ju)
                sRed[(ks * 4 + ju) * 128 + bloc] =
                    make_float4(redsum(acc[0 + ju]), redsum(acc[4 + ju]),
                                redsum(acc[8 + ju]), redsum(acc[12 + ju]));
            __syncthreads();
            sv = sRed[(0 * 4 + aju) * 128 + ab];
            #pragma unroll
            for (int g = 1; g < 4; ++g) {
                float4 v = sRed[(g * 4 + aju) * 128 + ab];
                sv.x += v.x; sv.y += v.y; sv.z += v.z; sv.w += v.w;
            }
            float xv = g_xT[(t + 1) * Bsz + bga];
            float gi = sv.x + fmaf(sWx[0 * 4 + aju], xv, sB0[0 * 4 + aju]);
            float gf = sv.y + fmaf(sWx[1 * 4 + aju], xv, sB0[1 * 4 + aju]);
            float gg = sv.z + fmaf(sWx[2 * 4 + aju], xv, sB0[2 * 4 + aju]);
            float go = sv.w + fmaf(sWx[3 * 4 + aju], xv, sB0[3 * 4 + aju]);
            float cn = sigf(gf) * c0 + sigf(gi) * tanhf_(gg);
            c0 = cn;
            ((float*)g_h0p[pr])[(k2h * Bsz + bga) * 2 + hpar] = sigf(go) * tanhf_(cn);
            bar_arrive(&g_cntA);             // idA = t+3
        }

        // ---- wait for all h1(t), then output dot for batches {2cta, 2cta+1} ----
        bar_wait(&g_cntB, (unsigned)(t + 1) * NCTA);
        {
            if (tid < 256) {
                const unsigned long long* __restrict__ hc = g_h1p[nx];
                int half = tid >> 7;
                int kk   = tid & 127;
                int bb   = 2 * cta + half;
                float2 hv = unpack2(__ldcg(hc + kk * Bsz + bb));
                float part = hv.x * sWlin[2 * kk] + hv.y * sWlin[2 * kk + 1];
                #pragma unroll
                for (int off = 16; off > 0; off >>= 1)
                    part += __shfl_down_sync(0xffffffffu, part, off);
                if ((tid & 31) == 0) sOut[tid >> 5] = part;
            }
            __syncthreads();
            if (tid == 0) {
                out[(2 * cta + 0) * Tlen + t] = sOut[0] + sOut[1] + sOut[2] + sOut[3] + bl;
                out[(2 * cta + 1) * Tlen + t] = sOut[4] + sOut[5] + sOut[6] + sOut[7] + bl;
            }
        }

        if (t < Tlen - 1)
            bar_wait(&g_cntA, (unsigned)(t + 3) * NCTA);   // h0(t+1) visible
    }

    // reset counters for next launch
    __syncthreads();
    if (tid == 0) {
        __threadfence();
        unsigned old = atomicAdd(&g_done, 1u);
        if (old == NCTA - 1) {
            atomicExch(&g_cntA, 0u);
            atomicExch(&g_cntB, 0u);
            atomicExch(&g_done, 0u);
        }
    }
}

extern "C" void kernel_launch(void* const* d_in, const int* in_sizes, int n_in,
                              void* d_out, int out_size) {
    (void)in_sizes; (void)n_in; (void)out_size;
    lstm_fused<<<NCTA, NTH>>>(
        (const float*)d_in[0],
        (const float*)d_in[1], (const float*)d_in[2],
        (const float*)d_in[3], (const float*)d_in[4],
        (const float*)d_in[5], (const float*)d_in[6],
        (const float*)d_in[7], (const float*)d_in[8],
        (const float*)d_in[9], (const float*)d_in[10],
        (float*)d_out);
}